// round 15
// baseline (speedup 1.0000x reference)
#include <cuda_runtime.h>
#include <cuda_bf16.h>

#define BATCH 1024
#define SEQ   512
#define HID   64
#define GATES 256
#define NR    8
#define NCTA  (BATCH / NR)   // 128
#define NTHR  384            // 12 warps: 8 L2 (gates2) + 4 L1 (gates1 next)

typedef unsigned long long ull;

struct __align__(16) Smem {
    // Weight layout: W[k][col], col = j*4 + hq (cell j, gate hq: 0=i,1=f,2=g,3=o)
    float W1[HID][GATES];          //  64 KB (W_hh1)
    float W2[2 * HID][GATES];      // 128 KB ([W_ih2 ; W_hh2])
    float hb1[2][HID][NR];         //   4 KB h1 double-buffered [buf][k][row]
    float hb2[2][HID][NR];         //   4 KB h2 double-buffered
    float wih1v[GATES];
    float b1v[GATES];
    float b2v[GATES];
    float wlin[HID];
    float xs[2][NR];
    float outp[2][4][2][8];        // [buf][pair][row-in-pair][l2-warp]
    float blin;
};   // ~204 KB

__device__ __forceinline__ ull pk2(float lo, float hi) {
    ull r; asm("mov.b64 %0, {%1, %2};" : "=l"(r) : "f"(lo), "f"(hi)); return r;
}
__device__ __forceinline__ void unpk(ull v, float& lo, float& hi) {
    asm("mov.b64 {%0, %1}, %2;" : "=f"(lo), "=f"(hi) : "l"(v));
}
__device__ __forceinline__ void fma2(ull& d, ull a, ull b) {
    asm("fma.rn.f32x2 %0, %1, %2, %0;" : "+l"(d) : "l"(a), "l"(b));
}
__device__ __forceinline__ ull add2(ull a, ull b) {
    ull d; asm("add.rn.f32x2 %0, %1, %2;" : "=l"(d) : "l"(a), "l"(b)); return d;
}

// MUFU.TANH (sm_75+), rel err ~2e-5
__device__ __forceinline__ float tanh_fast(float x) {
    float r; asm("tanh.approx.f32 %0, %1;" : "=f"(r) : "f"(x)); return r;
}
__device__ __forceinline__ float sigf(float v) {
    return fmaf(0.5f, tanh_fast(0.5f * v), 0.5f);
}

__device__ __forceinline__ void fma16(float4 wv, ulonglong2 hA, ulonglong2 hB,
                                      ull acc[4][4]) {
    ull w;
    w = pk2(wv.x, wv.x);
    fma2(acc[0][0], hA.x, w); fma2(acc[0][1], hA.y, w);
    fma2(acc[0][2], hB.x, w); fma2(acc[0][3], hB.y, w);
    w = pk2(wv.y, wv.y);
    fma2(acc[1][0], hA.x, w); fma2(acc[1][1], hA.y, w);
    fma2(acc[1][2], hB.x, w); fma2(acc[1][3], hB.y, w);
    w = pk2(wv.z, wv.z);
    fma2(acc[2][0], hA.x, w); fma2(acc[2][1], hA.y, w);
    fma2(acc[2][2], hB.x, w); fma2(acc[2][3], hB.y, w);
    w = pk2(wv.w, wv.w);
    fma2(acc[3][0], hA.x, w); fma2(acc[3][1], hA.y, w);
    fma2(acc[3][2], hB.x, w); fma2(acc[3][3], hB.y, w);
}

// 8 strided k-steps, weights from SMEM
template <int WS, int HS>
__device__ __forceinline__ void gemm8s(const float* __restrict__ wp,
                                       const float* __restrict__ hp,
                                       ull acc[4][4]) {
#pragma unroll
    for (int m = 0; m < 8; m++) {
        float4 wv = *reinterpret_cast<const float4*>(wp + m * WS);
        ulonglong2 hA = *reinterpret_cast<const ulonglong2*>(hp + m * HS);
        ulonglong2 hB = *reinterpret_cast<const ulonglong2*>(hp + m * HS + 4);
        fma16(wv, hA, hB, acc);
    }
}

// 8 strided k-steps, weights from registers (loop-invariant cache)
template <int HS>
__device__ __forceinline__ void gemm8r(const float4* wreg,
                                       const float* __restrict__ hp,
                                       ull acc[4][4]) {
#pragma unroll
    for (int m = 0; m < 8; m++) {
        ulonglong2 hA = *reinterpret_cast<const ulonglong2*>(hp + m * HS);
        ulonglong2 hB = *reinterpret_cast<const ulonglong2*>(hp + m * HS + 4);
        fma16(wreg[m], hA, hB, acc);
    }
}

// LSTM cell for a packed row-pair.
__device__ __forceinline__ ull act2(ull ai, ull af, ull ag, ull ao,
                                    float& ca, float& cb) {
    float i0, i1, f0, f1, g0, g1, o0, o1;
    unpk(ai, i0, i1); unpk(af, f0, f1);
    unpk(ag, g0, g1); unpk(ao, o0, o1);
    float cA = sigf(f0) * ca + sigf(i0) * tanh_fast(g0);
    float cB = sigf(f1) * cb + sigf(i1) * tanh_fast(g1);
    ca = cA; cb = cB;
    return pk2(sigf(o0) * tanh_fast(cA), sigf(o1) * tanh_fast(cB));
}

__global__ void __launch_bounds__(NTHR, 1)
lstm_persistent_kernel(const float* __restrict__ x,
                       const float* __restrict__ Wih1, const float* __restrict__ Whh1,
                       const float* __restrict__ bih1, const float* __restrict__ bhh1,
                       const float* __restrict__ Wih2, const float* __restrict__ Whh2,
                       const float* __restrict__ bih2, const float* __restrict__ bhh2,
                       const float* __restrict__ Wlin, const float* __restrict__ blin,
                       float* __restrict__ out) {
    extern __shared__ char smem_raw[];
    Smem& sm = *reinterpret_cast<Smem*>(smem_raw);

    const int tid  = threadIdx.x;
    const int wid  = tid >> 5;
    const int lane = tid & 31;
    const int row0 = blockIdx.x * NR;

    // ---- one-time staging ----
    for (int i = tid; i < GATES * HID; i += NTHR) {
        int gsrc = i >> 6, k = i & 63;
        int col = (gsrc & 63) * 4 + (gsrc >> 6);
        sm.W1[k][col]      = Whh1[i];
        sm.W2[k][col]      = Wih2[i];
        sm.W2[64 + k][col] = Whh2[i];
    }
    for (int gsrc = tid; gsrc < GATES; gsrc += NTHR) {
        int col = (gsrc & 63) * 4 + (gsrc >> 6);
        sm.wih1v[col] = Wih1[gsrc];
        sm.b1v[col]   = bih1[gsrc] + bhh1[gsrc];
        sm.b2v[col]   = bih2[gsrc] + bhh2[gsrc];
    }
    if (tid < HID) sm.wlin[tid] = Wlin[tid];
    if (tid == 0)  sm.blin = blin[0];
    for (int i = tid; i < 2 * HID * NR; i += NTHR) {
        reinterpret_cast<float*>(sm.hb1)[i] = 0.0f;
        reinterpret_cast<float*>(sm.hb2)[i] = 0.0f;
    }
    if (tid < NR) {
        sm.xs[1][tid] = x[(row0 + tid) * SEQ + 0];  // x(0) for prologue
        sm.xs[0][tid] = x[(row0 + tid) * SEQ + 1];  // x(1) for GEMM(0)
    }
    __syncthreads();

    const bool isL1 = (wid >= 8);
    // L2: warp owns 8 cells; lane = kq*8 + cell-in-warp; k-interleave kq+4m
    // L1: warp owns 16 cells; lane = kh*16 + cell-in-warp; k-interleave kh+2m
    const int kq   = lane >> 3;                      // L2 k-quarter / owned pair
    const int kh   = lane >> 4;                      // L1 k-half
    const int j    = isL1 ? ((wid - 8) * 16 + (lane & 15)) : (wid * 8 + (lane & 7));
    const int c4   = j * 4;

    // register-resident weight cache: 16 of this thread's 32 k-slices
    float4 wreg[16];
    if (!isL1) {
        const float* wp = &sm.W2[kq][c4];
#pragma unroll
        for (int m = 0; m < 8; m++) {
            wreg[m]     = *reinterpret_cast<const float4*>(wp + m * 4 * GATES);         // h1-part m 0..7
            wreg[8 + m] = *reinterpret_cast<const float4*>(wp + (16 + m) * 4 * GATES);  // h2-part m 0..7
        }
    } else {
        const float* wp = &sm.W1[kh][c4];
#pragma unroll
        for (int m = 0; m < 16; m++)
            wreg[m] = *reinterpret_cast<const float4*>(wp + m * 2 * GATES);             // m 0..15
    }

    // c-state: L2 lane holds c2 for pair kq; L1 lane c1 for pairs 2kh, 2kh+1
    float cs[4] = {0.f, 0.f, 0.f, 0.f};
    const float wl = sm.wlin[j];

    // ---- prologue: h1(0) = act(b1 + x(0)*wih1), L1 warps -> hb1[0] ----
    if (isL1) {
        float4 wiv = *reinterpret_cast<const float4*>(&sm.wih1v[c4]);
        float4 bv  = *reinterpret_cast<const float4*>(&sm.b1v[c4]);
        ulonglong2 xq = *reinterpret_cast<const ulonglong2*>(&sm.xs[1][4 * kh]);
        float wivf[4] = {wiv.x, wiv.y, wiv.z, wiv.w};
        float bvf[4]  = {bv.x, bv.y, bv.z, bv.w};
        ull gp0[4], gp1[4];
#pragma unroll
        for (int q = 0; q < 4; q++) {
            ull b = pk2(bvf[q], bvf[q]);
            ull w = pk2(wivf[q], wivf[q]);
            gp0[q] = b; fma2(gp0[q], xq.x, w);
            gp1[q] = b; fma2(gp1[q], xq.y, w);
        }
        ull h0p = act2(gp0[0], gp0[1], gp0[2], gp0[3], cs[0], cs[1]);
        ull h1p = act2(gp1[0], gp1[1], gp1[2], gp1[3], cs[2], cs[3]);
        *reinterpret_cast<ulonglong2*>(&sm.hb1[0][j][4 * kh]) = make_ulonglong2(h0p, h1p);
    }
    __syncthreads();

    for (int t = 0; t < SEQ; t++) {
        const int cur = t & 1, nxt = cur ^ 1;

        // finalize out[t-1] from outp[cur] (written during step t-1)
        if (t > 0 && tid < NR) {
            const float* op = &sm.outp[cur][tid >> 1][tid & 1][0];
            float4 a = *reinterpret_cast<const float4*>(op);
            float4 b = *reinterpret_cast<const float4*>(op + 4);
            out[(row0 + tid) * SEQ + (t - 1)] =
                sm.blin + ((a.x + a.y) + (a.z + a.w)) + ((b.x + b.y) + (b.z + b.w));
        }

        // ===== GEMM phase (pure accumulate, bias added post-reduce) =====
        ull acc[4][4];
#pragma unroll
        for (int q = 0; q < 4; q++)
#pragma unroll
            for (int p = 0; p < 4; p++) acc[q][p] = 0ull;

        if (!isL1) {
            // gates2(t): lane k = kq+4m; m<16 -> h1(t), m>=16 -> h2(t-1)
            const float* wp  = &sm.W2[kq][c4];
            const float* h1p = &sm.hb1[cur][kq][0];
            const float* h2p = &sm.hb2[cur][kq][0];
            gemm8r<4 * NR>(wreg,     h1p,              acc);                 // m  0..7  (regs)
            gemm8s<4 * GATES, 4 * NR>(wp + 8 * 4 * GATES, h1p + 8 * 4 * NR, acc); // m 8..15
            gemm8r<4 * NR>(wreg + 8, h2p,              acc);                 // m 16..23 (regs)
            gemm8s<4 * GATES, 4 * NR>(wp + 24 * 4 * GATES, h2p + 8 * 4 * NR, acc); // m 24..31
        } else {
            // gates1(t+1): lane k = kh+2m over h1(t)
            const float* wp = &sm.W1[kh][c4];
            const float* hp = &sm.hb1[cur][kh][0];
            gemm8r<2 * NR>(wreg,     hp,              acc);                  // m  0..7  (regs)
            gemm8r<2 * NR>(wreg + 8, hp + 8 * 2 * NR, acc);                  // m  8..15 (regs)
            gemm8s<2 * GATES, 2 * NR>(wp + 16 * 2 * GATES, hp + 16 * 2 * NR, acc);
            gemm8s<2 * GATES, 2 * NR>(wp + 24 * 2 * GATES, hp + 24 * 2 * NR, acc);
        }

        // ===== intra-warp k-reduce + ACT (no SMEM exchange, no mid barrier) =====
        if (!isL1) {
            // 4-way butterfly: xor-16 (kq^2), xor-8 (kq^1); lane ends with pair kq
            const bool lowkq = (kq < 2);
            ull a0[4], a1[4];
#pragma unroll
            for (int q = 0; q < 4; q++) {
                ull s0 = lowkq ? acc[q][2] : acc[q][0];
                ull s1 = lowkq ? acc[q][3] : acc[q][1];
                ull r0 = __shfl_xor_sync(0xffffffffu, s0, 16);
                ull r1 = __shfl_xor_sync(0xffffffffu, s1, 16);
                ull k0 = lowkq ? acc[q][0] : acc[q][2];
                ull k1 = lowkq ? acc[q][1] : acc[q][3];
                a0[q] = add2(k0, r0);
                a1[q] = add2(k1, r1);
            }
            const bool evenkq = ((kq & 1) == 0);
            float4 bv = *reinterpret_cast<const float4*>(&sm.b2v[c4]);
            float bvf[4] = {bv.x, bv.y, bv.z, bv.w};
            ull g[4];
#pragma unroll
            for (int q = 0; q < 4; q++) {
                ull s = evenkq ? a1[q] : a0[q];
                ull r = __shfl_xor_sync(0xffffffffu, s, 8);
                ull k = evenkq ? a0[q] : a1[q];
                g[q] = add2(add2(k, r), pk2(bvf[q], bvf[q]));
            }
            ull h2p = act2(g[0], g[1], g[2], g[3], cs[0], cs[1]);
            *reinterpret_cast<ull*>(&sm.hb2[nxt][j][2 * kq]) = h2p;

            // out partials: octet-reduce over this warp's 8 cells (lanes same kq)
            float h0, h1;
            unpk(h2p, h0, h1);
            float p0 = wl * h0, p1 = wl * h1;
#pragma unroll
            for (int off = 1; off < 8; off <<= 1) {
                p0 += __shfl_xor_sync(0xffffffffu, p0, off);
                p1 += __shfl_xor_sync(0xffffffffu, p1, off);
            }
            if ((lane & 7) == 0) {
                sm.outp[nxt][kq][0][wid] = p0;
                sm.outp[nxt][kq][1][wid] = p1;
            }
        } else {
            // 2-way reduce via xor-16; lane ends with pairs 2kh, 2kh+1
            ull gp0[4], gp1[4];
#pragma unroll
            for (int q = 0; q < 4; q++) {
                ull s0 = kh ? acc[q][0] : acc[q][2];
                ull s1 = kh ? acc[q][1] : acc[q][3];
                ull r0 = __shfl_xor_sync(0xffffffffu, s0, 16);
                ull r1 = __shfl_xor_sync(0xffffffffu, s1, 16);
                ull o0 = kh ? acc[q][2] : acc[q][0];
                ull o1 = kh ? acc[q][3] : acc[q][1];
                gp0[q] = add2(o0, r0);
                gp1[q] = add2(o1, r1);
            }
            // add bias + x(t+1) term post-reduce
            float4 wiv = *reinterpret_cast<const float4*>(&sm.wih1v[c4]);
            float4 bv  = *reinterpret_cast<const float4*>(&sm.b1v[c4]);
            ulonglong2 xq = *reinterpret_cast<const ulonglong2*>(&sm.xs[cur][4 * kh]);
            float wivf[4] = {wiv.x, wiv.y, wiv.z, wiv.w};
            float bvf[4]  = {bv.x, bv.y, bv.z, bv.w};
#pragma unroll
            for (int q = 0; q < 4; q++) {
                ull w = pk2(wivf[q], wivf[q]);
                ull t0 = pk2(bvf[q], bvf[q]); fma2(t0, xq.x, w);
                ull t1 = pk2(bvf[q], bvf[q]); fma2(t1, xq.y, w);
                gp0[q] = add2(gp0[q], t0);
                gp1[q] = add2(gp1[q], t1);
            }
            ull h0p = act2(gp0[0], gp0[1], gp0[2], gp0[3], cs[0], cs[1]);
            ull h1p = act2(gp1[0], gp1[1], gp1[2], gp1[3], cs[2], cs[3]);
            *reinterpret_cast<ulonglong2*>(&sm.hb1[nxt][j][4 * kh]) =
                make_ulonglong2(h0p, h1p);
        }
        // prefetch x(t+2) into xs[nxt]
        if (tid < NR && (t + 2) < SEQ)
            sm.xs[nxt][tid] = x[(row0 + tid) * SEQ + t + 2];

        __syncthreads();   // single per-step hand-off
    }

    // finalize out[SEQ-1] from outp[SEQ & 1]
    if (tid < NR) {
        const float* op = &sm.outp[SEQ & 1][tid >> 1][tid & 1][0];
        float4 a = *reinterpret_cast<const float4*>(op);
        float4 b = *reinterpret_cast<const float4*>(op + 4);
        out[(row0 + tid) * SEQ + (SEQ - 1)] =
            sm.blin + ((a.x + a.y) + (a.z + a.w)) + ((b.x + b.y) + (b.z + b.w));
    }
}

extern "C" void kernel_launch(void* const* d_in, const int* in_sizes, int n_in,
                              void* d_out, int out_size) {
    const float* x     = (const float*)d_in[0];
    const float* Wih1  = (const float*)d_in[1];
    const float* Whh1  = (const float*)d_in[2];
    const float* bih1  = (const float*)d_in[3];
    const float* bhh1  = (const float*)d_in[4];
    const float* Wih2  = (const float*)d_in[5];
    const float* Whh2  = (const float*)d_in[6];
    const float* bih2  = (const float*)d_in[7];
    const float* bhh2  = (const float*)d_in[8];
    const float* Wlin  = (const float*)d_in[9];
    const float* blin  = (const float*)d_in[10];
    float* out = (float*)d_out;

    (void)in_sizes; (void)n_in; (void)out_size;

    static_assert(sizeof(Smem) <= 232448, "smem over sm_103a opt-in limit");
    cudaFuncSetAttribute(lstm_persistent_kernel,
                         cudaFuncAttributeMaxDynamicSharedMemorySize,
                         (int)sizeof(Smem));
    lstm_persistent_kernel<<<NCTA, NTHR, sizeof(Smem)>>>(
        x, Wih1, Whh1, bih1, bhh1, Wih2, Whh2, bih2, bhh2, Wlin, blin, out);
}

// round 16
// speedup vs baseline: 1.0228x; 1.0228x over previous
#include <cuda_runtime.h>
#include <cuda_bf16.h>

#define BATCH 1024
#define SEQ   512
#define HID   64
#define GATES 256
#define NR    8
#define NCTA  (BATCH / NR)   // 128
#define NTHR  384            // 12 warps: 8 L2 (gates2) + 4 L1 (gates1 next)

typedef unsigned long long ull;

struct __align__(16) Smem {
    // Weight layout: W[k][col], col = j*4 + hq (cell j, gate hq: 0=i,1=f,2=g,3=o)
    float W1[HID][GATES];          //  64 KB (W_hh1)
    float W2[2 * HID][GATES];      // 128 KB ([W_ih2 ; W_hh2])
    float hb1[2][HID][NR];         //   4 KB h1 double-buffered [buf][k][row]
    float hb2[2][HID][NR];         //   4 KB h2 double-buffered
    float wih1v[GATES];
    float b1v[GATES];
    float b2v[GATES];
    float wlin[HID];
    float xs[2][NR];
    float outp[2][4][2][8];        // [buf][pair][row-in-pair][l2-warp]
    float blin;
};   // ~204 KB

__device__ __forceinline__ ull pk2(float lo, float hi) {
    ull r; asm("mov.b64 %0, {%1, %2};" : "=l"(r) : "f"(lo), "f"(hi)); return r;
}
__device__ __forceinline__ void unpk(ull v, float& lo, float& hi) {
    asm("mov.b64 {%0, %1}, %2;" : "=f"(lo), "=f"(hi) : "l"(v));
}
__device__ __forceinline__ void fma2(ull& d, ull a, ull b) {
    asm("fma.rn.f32x2 %0, %1, %2, %0;" : "+l"(d) : "l"(a), "l"(b));
}
__device__ __forceinline__ ull add2(ull a, ull b) {
    ull d; asm("add.rn.f32x2 %0, %1, %2;" : "=l"(d) : "l"(a), "l"(b)); return d;
}

// MUFU.TANH (sm_75+), rel err ~2e-5
__device__ __forceinline__ float tanh_fast(float x) {
    float r; asm("tanh.approx.f32 %0, %1;" : "=f"(r) : "f"(x)); return r;
}
__device__ __forceinline__ float sigf(float v) {
    return fmaf(0.5f, tanh_fast(0.5f * v), 0.5f);
}

__device__ __forceinline__ void fma16(float4 wv, ulonglong2 hA, ulonglong2 hB,
                                      ull acc[4][4]) {
    ull w;
    w = pk2(wv.x, wv.x);
    fma2(acc[0][0], hA.x, w); fma2(acc[0][1], hA.y, w);
    fma2(acc[0][2], hB.x, w); fma2(acc[0][3], hB.y, w);
    w = pk2(wv.y, wv.y);
    fma2(acc[1][0], hA.x, w); fma2(acc[1][1], hA.y, w);
    fma2(acc[1][2], hB.x, w); fma2(acc[1][3], hB.y, w);
    w = pk2(wv.z, wv.z);
    fma2(acc[2][0], hA.x, w); fma2(acc[2][1], hA.y, w);
    fma2(acc[2][2], hB.x, w); fma2(acc[2][3], hB.y, w);
    w = pk2(wv.w, wv.w);
    fma2(acc[3][0], hA.x, w); fma2(acc[3][1], hA.y, w);
    fma2(acc[3][2], hB.x, w); fma2(acc[3][3], hB.y, w);
}

// 8 strided k-steps, weights from SMEM
template <int WS, int HS>
__device__ __forceinline__ void gemm8s(const float* __restrict__ wp,
                                       const float* __restrict__ hp,
                                       ull acc[4][4]) {
#pragma unroll
    for (int m = 0; m < 8; m++) {
        float4 wv = *reinterpret_cast<const float4*>(wp + m * WS);
        ulonglong2 hA = *reinterpret_cast<const ulonglong2*>(hp + m * HS);
        ulonglong2 hB = *reinterpret_cast<const ulonglong2*>(hp + m * HS + 4);
        fma16(wv, hA, hB, acc);
    }
}

// 8 strided k-steps, weights from registers (loop-invariant cache)
template <int HS>
__device__ __forceinline__ void gemm8r(const float4* wreg,
                                       const float* __restrict__ hp,
                                       ull acc[4][4]) {
#pragma unroll
    for (int m = 0; m < 8; m++) {
        ulonglong2 hA = *reinterpret_cast<const ulonglong2*>(hp + m * HS);
        ulonglong2 hB = *reinterpret_cast<const ulonglong2*>(hp + m * HS + 4);
        fma16(wreg[m], hA, hB, acc);
    }
}

// LSTM cell for a packed row-pair.
__device__ __forceinline__ ull act2(ull ai, ull af, ull ag, ull ao,
                                    float& ca, float& cb) {
    float i0, i1, f0, f1, g0, g1, o0, o1;
    unpk(ai, i0, i1); unpk(af, f0, f1);
    unpk(ag, g0, g1); unpk(ao, o0, o1);
    float cA = sigf(f0) * ca + sigf(i0) * tanh_fast(g0);
    float cB = sigf(f1) * cb + sigf(i1) * tanh_fast(g1);
    ca = cA; cb = cB;
    return pk2(sigf(o0) * tanh_fast(cA), sigf(o1) * tanh_fast(cB));
}

// One timestep with compile-time buffer parity (CUR). Expanded twice per loop
// iteration so all hb1/hb2/xs/outp bases are immediate offsets in SASS.
#define STEP_BODY(CUR, NXT, tvar)                                                     \
    {                                                                                 \
        if ((tvar) > 0 && tid < NR) {                                                 \
            const float* op = &sm.outp[CUR][tid >> 1][tid & 1][0];                    \
            float4 a = *reinterpret_cast<const float4*>(op);                          \
            float4 b = *reinterpret_cast<const float4*>(op + 4);                      \
            out[(row0 + tid) * SEQ + ((tvar) - 1)] =                                  \
                sm.blin + ((a.x + a.y) + (a.z + a.w)) + ((b.x + b.y) + (b.z + b.w));  \
        }                                                                             \
        ull acc[4][4];                                                                \
        _Pragma("unroll")                                                             \
        for (int q = 0; q < 4; q++)                                                   \
            _Pragma("unroll")                                                         \
            for (int p = 0; p < 4; p++) acc[q][p] = 0ull;                             \
        if (!isL1) {                                                                  \
            const float* wp  = &sm.W2[kq][c4];                                        \
            const float* h1p = &sm.hb1[CUR][kq][0];                                   \
            const float* h2p = &sm.hb2[CUR][kq][0];                                   \
            gemm8r<4 * NR>(wreg, h1p, acc);                                           \
            gemm8s<4 * GATES, 4 * NR>(wp +  8 * 4 * GATES, h1p + 8 * 4 * NR, acc);    \
            gemm8s<4 * GATES, 4 * NR>(wp + 16 * 4 * GATES, h2p,              acc);    \
            gemm8s<4 * GATES, 4 * NR>(wp + 24 * 4 * GATES, h2p + 8 * 4 * NR, acc);    \
        } else {                                                                      \
            const float* wp = &sm.W1[kh][c4];                                         \
            const float* hp = &sm.hb1[CUR][kh][0];                                    \
            gemm8r<2 * NR>(wreg, hp, acc);                                            \
            gemm8s<2 * GATES, 2 * NR>(wp +  8 * 2 * GATES, hp +  8 * 2 * NR, acc);    \
            gemm8s<2 * GATES, 2 * NR>(wp + 16 * 2 * GATES, hp + 16 * 2 * NR, acc);    \
            gemm8s<2 * GATES, 2 * NR>(wp + 24 * 2 * GATES, hp + 24 * 2 * NR, acc);    \
        }                                                                             \
        if (!isL1) {                                                                  \
            const bool lowkq = (kq < 2);                                              \
            ull a0[4], a1[4];                                                         \
            _Pragma("unroll")                                                         \
            for (int q = 0; q < 4; q++) {                                             \
                ull s0 = lowkq ? acc[q][2] : acc[q][0];                               \
                ull s1 = lowkq ? acc[q][3] : acc[q][1];                               \
                ull r0 = __shfl_xor_sync(0xffffffffu, s0, 16);                        \
                ull r1 = __shfl_xor_sync(0xffffffffu, s1, 16);                        \
                ull k0 = lowkq ? acc[q][0] : acc[q][2];                               \
                ull k1 = lowkq ? acc[q][1] : acc[q][3];                               \
                a0[q] = add2(k0, r0);                                                 \
                a1[q] = add2(k1, r1);                                                 \
            }                                                                         \
            const bool evenkq = ((kq & 1) == 0);                                      \
            float4 bv = *reinterpret_cast<const float4*>(&sm.b2v[c4]);                \
            float bvf[4] = {bv.x, bv.y, bv.z, bv.w};                                  \
            ull g[4];                                                                 \
            _Pragma("unroll")                                                         \
            for (int q = 0; q < 4; q++) {                                             \
                ull s = evenkq ? a1[q] : a0[q];                                       \
                ull r = __shfl_xor_sync(0xffffffffu, s, 8);                           \
                ull k = evenkq ? a0[q] : a1[q];                                       \
                g[q] = add2(add2(k, r), pk2(bvf[q], bvf[q]));                         \
            }                                                                         \
            ull h2p = act2(g[0], g[1], g[2], g[3], cs[0], cs[1]);                     \
            *reinterpret_cast<ull*>(&sm.hb2[NXT][j][2 * kq]) = h2p;                   \
            float h0, h1;                                                             \
            unpk(h2p, h0, h1);                                                        \
            float p0 = wl * h0, p1 = wl * h1;                                         \
            _Pragma("unroll")                                                         \
            for (int off = 1; off < 8; off <<= 1) {                                   \
                p0 += __shfl_xor_sync(0xffffffffu, p0, off);                          \
                p1 += __shfl_xor_sync(0xffffffffu, p1, off);                          \
            }                                                                         \
            if ((lane & 7) == 0) {                                                    \
                sm.outp[NXT][kq][0][wid] = p0;                                        \
                sm.outp[NXT][kq][1][wid] = p1;                                        \
            }                                                                         \
        } else {                                                                      \
            ull gp0[4], gp1[4];                                                       \
            _Pragma("unroll")                                                         \
            for (int q = 0; q < 4; q++) {                                             \
                ull s0 = kh ? acc[q][0] : acc[q][2];                                  \
                ull s1 = kh ? acc[q][1] : acc[q][3];                                  \
                ull r0 = __shfl_xor_sync(0xffffffffu, s0, 16);                        \
                ull r1 = __shfl_xor_sync(0xffffffffu, s1, 16);                        \
                ull o0 = kh ? acc[q][2] : acc[q][0];                                  \
                ull o1 = kh ? acc[q][3] : acc[q][1];                                  \
                gp0[q] = add2(o0, r0);                                                \
                gp1[q] = add2(o1, r1);                                                \
            }                                                                         \
            float4 wiv = *reinterpret_cast<const float4*>(&sm.wih1v[c4]);             \
            float4 bv  = *reinterpret_cast<const float4*>(&sm.b1v[c4]);               \
            ulonglong2 xq = *reinterpret_cast<const ulonglong2*>(&sm.xs[CUR][4 * kh]);\
            float wivf[4] = {wiv.x, wiv.y, wiv.z, wiv.w};                             \
            float bvf[4]  = {bv.x, bv.y, bv.z, bv.w};                                 \
            _Pragma("unroll")                                                         \
            for (int q = 0; q < 4; q++) {                                             \
                ull w = pk2(wivf[q], wivf[q]);                                        \
                ull t0 = pk2(bvf[q], bvf[q]); fma2(t0, xq.x, w);                      \
                ull t1 = pk2(bvf[q], bvf[q]); fma2(t1, xq.y, w);                      \
                gp0[q] = add2(gp0[q], t0);                                            \
                gp1[q] = add2(gp1[q], t1);                                            \
            }                                                                         \
            ull h0p = act2(gp0[0], gp0[1], gp0[2], gp0[3], cs[0], cs[1]);             \
            ull h1p = act2(gp1[0], gp1[1], gp1[2], gp1[3], cs[2], cs[3]);              \
            *reinterpret_cast<ulonglong2*>(&sm.hb1[NXT][j][4 * kh]) =                 \
                make_ulonglong2(h0p, h1p);                                            \
        }                                                                             \
        if (tid < NR && ((tvar) + 2) < SEQ)                                           \
            sm.xs[NXT][tid] = x[(row0 + tid) * SEQ + (tvar) + 2];                     \
        __syncthreads();                                                              \
    }

__global__ void __launch_bounds__(NTHR, 1)
lstm_persistent_kernel(const float* __restrict__ x,
                       const float* __restrict__ Wih1, const float* __restrict__ Whh1,
                       const float* __restrict__ bih1, const float* __restrict__ bhh1,
                       const float* __restrict__ Wih2, const float* __restrict__ Whh2,
                       const float* __restrict__ bih2, const float* __restrict__ bhh2,
                       const float* __restrict__ Wlin, const float* __restrict__ blin,
                       float* __restrict__ out) {
    extern __shared__ char smem_raw[];
    Smem& sm = *reinterpret_cast<Smem*>(smem_raw);

    const int tid  = threadIdx.x;
    const int wid  = tid >> 5;
    const int lane = tid & 31;
    const int row0 = blockIdx.x * NR;

    // ---- one-time staging ----
    for (int i = tid; i < GATES * HID; i += NTHR) {
        int gsrc = i >> 6, k = i & 63;
        int col = (gsrc & 63) * 4 + (gsrc >> 6);
        sm.W1[k][col]      = Whh1[i];
        sm.W2[k][col]      = Wih2[i];
        sm.W2[64 + k][col] = Whh2[i];
    }
    for (int gsrc = tid; gsrc < GATES; gsrc += NTHR) {
        int col = (gsrc & 63) * 4 + (gsrc >> 6);
        sm.wih1v[col] = Wih1[gsrc];
        sm.b1v[col]   = bih1[gsrc] + bhh1[gsrc];
        sm.b2v[col]   = bih2[gsrc] + bhh2[gsrc];
    }
    if (tid < HID) sm.wlin[tid] = Wlin[tid];
    if (tid == 0)  sm.blin = blin[0];
    for (int i = tid; i < 2 * HID * NR; i += NTHR) {
        reinterpret_cast<float*>(sm.hb1)[i] = 0.0f;
        reinterpret_cast<float*>(sm.hb2)[i] = 0.0f;
    }
    if (tid < NR) {
        sm.xs[1][tid] = x[(row0 + tid) * SEQ + 0];  // x(0) for prologue
        sm.xs[0][tid] = x[(row0 + tid) * SEQ + 1];  // x(1) for GEMM(0)
    }
    __syncthreads();

    const bool isL1 = (wid >= 8);
    const int kq   = lane >> 3;                      // L2 k-quarter / owned pair
    const int kh   = lane >> 4;                      // L1 k-half
    const int j    = isL1 ? ((wid - 8) * 16 + (lane & 15)) : (wid * 8 + (lane & 7));
    const int c4   = j * 4;

    // register-resident weight cache: first 8 k-slices of this thread's strip
    float4 wreg[8];
    if (!isL1) {
        const float* wp = &sm.W2[kq][c4];
#pragma unroll
        for (int m = 0; m < 8; m++)
            wreg[m] = *reinterpret_cast<const float4*>(wp + m * 4 * GATES);
    } else {
        const float* wp = &sm.W1[kh][c4];
#pragma unroll
        for (int m = 0; m < 8; m++)
            wreg[m] = *reinterpret_cast<const float4*>(wp + m * 2 * GATES);
    }

    float cs[4] = {0.f, 0.f, 0.f, 0.f};
    const float wl = sm.wlin[j];

    // ---- prologue: h1(0) = act(b1 + x(0)*wih1), L1 warps -> hb1[0] ----
    if (isL1) {
        float4 wiv = *reinterpret_cast<const float4*>(&sm.wih1v[c4]);
        float4 bv  = *reinterpret_cast<const float4*>(&sm.b1v[c4]);
        ulonglong2 xq = *reinterpret_cast<const ulonglong2*>(&sm.xs[1][4 * kh]);
        float wivf[4] = {wiv.x, wiv.y, wiv.z, wiv.w};
        float bvf[4]  = {bv.x, bv.y, bv.z, bv.w};
        ull gp0[4], gp1[4];
#pragma unroll
        for (int q = 0; q < 4; q++) {
            ull b = pk2(bvf[q], bvf[q]);
            ull w = pk2(wivf[q], wivf[q]);
            gp0[q] = b; fma2(gp0[q], xq.x, w);
            gp1[q] = b; fma2(gp1[q], xq.y, w);
        }
        ull h0p = act2(gp0[0], gp0[1], gp0[2], gp0[3], cs[0], cs[1]);
        ull h1p = act2(gp1[0], gp1[1], gp1[2], gp1[3], cs[2], cs[3]);
        *reinterpret_cast<ulonglong2*>(&sm.hb1[0][j][4 * kh]) = make_ulonglong2(h0p, h1p);
    }
    __syncthreads();

    // unrolled x2: compile-time parity per copy
    for (int t = 0; t < SEQ; t += 2) {
        STEP_BODY(0, 1, t)
        STEP_BODY(1, 0, t + 1)
    }

    // finalize out[SEQ-1] from outp[SEQ & 1]
    if (tid < NR) {
        const float* op = &sm.outp[SEQ & 1][tid >> 1][tid & 1][0];
        float4 a = *reinterpret_cast<const float4*>(op);
        float4 b = *reinterpret_cast<const float4*>(op + 4);
        out[(row0 + tid) * SEQ + (SEQ - 1)] =
            sm.blin + ((a.x + a.y) + (a.z + a.w)) + ((b.x + b.y) + (b.z + b.w));
    }
}

extern "C" void kernel_launch(void* const* d_in, const int* in_sizes, int n_in,
                              void* d_out, int out_size) {
    const float* x     = (const float*)d_in[0];
    const float* Wih1  = (const float*)d_in[1];
    const float* Whh1  = (const float*)d_in[2];
    const float* bih1  = (const float*)d_in[3];
    const float* bhh1  = (const float*)d_in[4];
    const float* Wih2  = (const float*)d_in[5];
    const float* Whh2  = (const float*)d_in[6];
    const float* bih2  = (const float*)d_in[7];
    const float* bhh2  = (const float*)d_in[8];
    const float* Wlin  = (const float*)d_in[9];
    const float* blin  = (const float*)d_in[10];
    float* out = (float*)d_out;

    (void)in_sizes; (void)n_in; (void)out_size;

    static_assert(sizeof(Smem) <= 232448, "smem over sm_103a opt-in limit");
    cudaFuncSetAttribute(lstm_persistent_kernel,
                         cudaFuncAttributeMaxDynamicSharedMemorySize,
                         (int)sizeof(Smem));
    lstm_persistent_kernel<<<NCTA, NTHR, sizeof(Smem)>>>(
        x, Wih1, Whh1, bih1, bhh1, Wih2, Whh2, bih2, bhh2, Wlin, blin, out);
}

// round 17
// speedup vs baseline: 1.0478x; 1.0245x over previous
#include <cuda_runtime.h>
#include <cuda_bf16.h>

#define BATCH 1024
#define SEQ   512
#define HID   64
#define GATES 256
#define NR    8
#define NCTA  (BATCH / NR)   // 128
#define NTHR  384            // 12 warps: 8 L2 (gates2) + 4 L1 (gates1 next)

typedef unsigned long long ull;

struct __align__(16) Smem {
    // Weight layout: W[k][col], col = j*4 + hq (cell j, gate hq: 0=i,1=f,2=g,3=o)
    float W1[HID][GATES];          //  64 KB (W_hh1)
    float W2[2 * HID][GATES];      // 128 KB ([W_ih2 ; W_hh2])
    float hb1[2][HID][NR];         //   4 KB h1 double-buffered [buf][k][row]
    float hb2[2][HID][NR];         //   4 KB h2 double-buffered
    float xT[SEQ + 1][NR];         //  ~16 KB x transposed [t][row] (+1 pad row)
    float wih1v[GATES];
    float b1v[GATES];
    float b2v[GATES];
    float wlin[HID];
    float outp[2][4][2][8];        // [buf][pair][row-in-pair][l2-warp]
    float blin;
};   // ~220 KB

__device__ __forceinline__ ull pk2(float lo, float hi) {
    ull r; asm("mov.b64 %0, {%1, %2};" : "=l"(r) : "f"(lo), "f"(hi)); return r;
}
__device__ __forceinline__ void unpk(ull v, float& lo, float& hi) {
    asm("mov.b64 {%0, %1}, %2;" : "=f"(lo), "=f"(hi) : "l"(v));
}
__device__ __forceinline__ void fma2(ull& d, ull a, ull b) {
    asm("fma.rn.f32x2 %0, %1, %2, %0;" : "+l"(d) : "l"(a), "l"(b));
}
__device__ __forceinline__ ull add2(ull a, ull b) {
    ull d; asm("add.rn.f32x2 %0, %1, %2;" : "=l"(d) : "l"(a), "l"(b)); return d;
}

// MUFU.TANH (sm_75+), rel err ~2e-5
__device__ __forceinline__ float tanh_fast(float x) {
    float r; asm("tanh.approx.f32 %0, %1;" : "=f"(r) : "f"(x)); return r;
}
__device__ __forceinline__ float sigf(float v) {
    return fmaf(0.5f, tanh_fast(0.5f * v), 0.5f);
}

__device__ __forceinline__ void fma16(float4 wv, ulonglong2 hA, ulonglong2 hB,
                                      ull acc[4][4]) {
    ull w;
    w = pk2(wv.x, wv.x);
    fma2(acc[0][0], hA.x, w); fma2(acc[0][1], hA.y, w);
    fma2(acc[0][2], hB.x, w); fma2(acc[0][3], hB.y, w);
    w = pk2(wv.y, wv.y);
    fma2(acc[1][0], hA.x, w); fma2(acc[1][1], hA.y, w);
    fma2(acc[1][2], hB.x, w); fma2(acc[1][3], hB.y, w);
    w = pk2(wv.z, wv.z);
    fma2(acc[2][0], hA.x, w); fma2(acc[2][1], hA.y, w);
    fma2(acc[2][2], hB.x, w); fma2(acc[2][3], hB.y, w);
    w = pk2(wv.w, wv.w);
    fma2(acc[3][0], hA.x, w); fma2(acc[3][1], hA.y, w);
    fma2(acc[3][2], hB.x, w); fma2(acc[3][3], hB.y, w);
}

// 8 strided k-steps, weights from SMEM
template <int WS, int HS>
__device__ __forceinline__ void gemm8s(const float* __restrict__ wp,
                                       const float* __restrict__ hp,
                                       ull acc[4][4]) {
#pragma unroll
    for (int m = 0; m < 8; m++) {
        float4 wv = *reinterpret_cast<const float4*>(wp + m * WS);
        ulonglong2 hA = *reinterpret_cast<const ulonglong2*>(hp + m * HS);
        ulonglong2 hB = *reinterpret_cast<const ulonglong2*>(hp + m * HS + 4);
        fma16(wv, hA, hB, acc);
    }
}

// 8 strided k-steps, weights from registers (loop-invariant cache)
template <int HS>
__device__ __forceinline__ void gemm8r(const float4* wreg,
                                       const float* __restrict__ hp,
                                       ull acc[4][4]) {
#pragma unroll
    for (int m = 0; m < 8; m++) {
        ulonglong2 hA = *reinterpret_cast<const ulonglong2*>(hp + m * HS);
        ulonglong2 hB = *reinterpret_cast<const ulonglong2*>(hp + m * HS + 4);
        fma16(wreg[m], hA, hB, acc);
    }
}

// LSTM cell for a packed row-pair.
__device__ __forceinline__ ull act2(ull ai, ull af, ull ag, ull ao,
                                    float& ca, float& cb) {
    float i0, i1, f0, f1, g0, g1, o0, o1;
    unpk(ai, i0, i1); unpk(af, f0, f1);
    unpk(ag, g0, g1); unpk(ao, o0, o1);
    float cA = sigf(f0) * ca + sigf(i0) * tanh_fast(g0);
    float cB = sigf(f1) * cb + sigf(i1) * tanh_fast(g1);
    ca = cA; cb = cB;
    return pk2(sigf(o0) * tanh_fast(cA), sigf(o1) * tanh_fast(cB));
}

// One timestep with compile-time buffer parity (CUR).
#define STEP_BODY(CUR, NXT, tvar)                                                     \
    {                                                                                 \
        if ((tvar) > 0 && tid < NR) {                                                 \
            const float* op = &sm.outp[CUR][tid >> 1][tid & 1][0];                    \
            float4 a = *reinterpret_cast<const float4*>(op);                          \
            float4 b = *reinterpret_cast<const float4*>(op + 4);                      \
            out[(row0 + tid) * SEQ + ((tvar) - 1)] =                                  \
                sm.blin + ((a.x + a.y) + (a.z + a.w)) + ((b.x + b.y) + (b.z + b.w));  \
        }                                                                             \
        ull acc[4][4];                                                                \
        _Pragma("unroll")                                                             \
        for (int q = 0; q < 4; q++)                                                   \
            _Pragma("unroll")                                                         \
            for (int p = 0; p < 4; p++) acc[q][p] = 0ull;                             \
        if (!isL1) {                                                                  \
            const float* wp  = &sm.W2[kq][c4];                                        \
            const float* h1p = &sm.hb1[CUR][kq][0];                                   \
            const float* h2p = &sm.hb2[CUR][kq][0];                                   \
            gemm8r<4 * NR>(wreg, h1p, acc);                                           \
            gemm8s<4 * GATES, 4 * NR>(wp +  8 * 4 * GATES, h1p + 8 * 4 * NR, acc);    \
            gemm8s<4 * GATES, 4 * NR>(wp + 16 * 4 * GATES, h2p,              acc);    \
            gemm8s<4 * GATES, 4 * NR>(wp + 24 * 4 * GATES, h2p + 8 * 4 * NR, acc);    \
        } else {                                                                      \
            const float* wp = &sm.W1[kh][c4];                                         \
            const float* hp = &sm.hb1[CUR][kh][0];                                    \
            gemm8r<2 * NR>(wreg, hp, acc);                                            \
            gemm8s<2 * GATES, 2 * NR>(wp +  8 * 2 * GATES, hp +  8 * 2 * NR, acc);    \
            gemm8s<2 * GATES, 2 * NR>(wp + 16 * 2 * GATES, hp + 16 * 2 * NR, acc);    \
            gemm8s<2 * GATES, 2 * NR>(wp + 24 * 2 * GATES, hp + 24 * 2 * NR, acc);    \
        }                                                                             \
        if (!isL1) {                                                                  \
            const bool lowkq = (kq < 2);                                              \
            ull a0[4], a1[4];                                                         \
            _Pragma("unroll")                                                         \
            for (int q = 0; q < 4; q++) {                                             \
                ull s0 = lowkq ? acc[q][2] : acc[q][0];                               \
                ull s1 = lowkq ? acc[q][3] : acc[q][1];                               \
                ull r0 = __shfl_xor_sync(0xffffffffu, s0, 16);                        \
                ull r1 = __shfl_xor_sync(0xffffffffu, s1, 16);                        \
                ull k0 = lowkq ? acc[q][0] : acc[q][2];                               \
                ull k1 = lowkq ? acc[q][1] : acc[q][3];                               \
                a0[q] = add2(k0, r0);                                                 \
                a1[q] = add2(k1, r1);                                                 \
            }                                                                         \
            const bool evenkq = ((kq & 1) == 0);                                      \
            ull g[4];                                                                 \
            _Pragma("unroll")                                                         \
            for (int q = 0; q < 4; q++) {                                             \
                ull s = evenkq ? a1[q] : a0[q];                                       \
                ull r = __shfl_xor_sync(0xffffffffu, s, 8);                           \
                ull k = evenkq ? a0[q] : a1[q];                                       \
                g[q] = add2(add2(k, r), biasd[q]);                                    \
            }                                                                         \
            ull h2p = act2(g[0], g[1], g[2], g[3], cs[0], cs[1]);                     \
            *reinterpret_cast<ull*>(&sm.hb2[NXT][j][2 * kq]) = h2p;                   \
            float h0, h1;                                                             \
            unpk(h2p, h0, h1);                                                        \
            float p0 = wl * h0, p1 = wl * h1;                                         \
            _Pragma("unroll")                                                         \
            for (int off = 1; off < 8; off <<= 1) {                                   \
                p0 += __shfl_xor_sync(0xffffffffu, p0, off);                          \
                p1 += __shfl_xor_sync(0xffffffffu, p1, off);                          \
            }                                                                         \
            if ((lane & 7) == 0) {                                                    \
                sm.outp[NXT][kq][0][wid] = p0;                                        \
                sm.outp[NXT][kq][1][wid] = p1;                                        \
            }                                                                         \
        } else {                                                                      \
            ull gp0[4], gp1[4];                                                       \
            _Pragma("unroll")                                                         \
            for (int q = 0; q < 4; q++) {                                             \
                ull s0 = kh ? acc[q][0] : acc[q][2];                                  \
                ull s1 = kh ? acc[q][1] : acc[q][3];                                  \
                ull r0 = __shfl_xor_sync(0xffffffffu, s0, 16);                        \
                ull r1 = __shfl_xor_sync(0xffffffffu, s1, 16);                        \
                ull o0 = kh ? acc[q][2] : acc[q][0];                                  \
                ull o1 = kh ? acc[q][3] : acc[q][1];                                  \
                gp0[q] = add2(o0, r0);                                                \
                gp1[q] = add2(o1, r1);                                                \
            }                                                                         \
            ulonglong2 xq =                                                           \
                *reinterpret_cast<const ulonglong2*>(&sm.xT[(tvar) + 1][4 * kh]);     \
            _Pragma("unroll")                                                         \
            for (int q = 0; q < 4; q++) {                                             \
                ull t0 = biasd[q]; fma2(t0, xq.x, wd[q]);                             \
                ull t1 = biasd[q]; fma2(t1, xq.y, wd[q]);                             \
                gp0[q] = add2(gp0[q], t0);                                            \
                gp1[q] = add2(gp1[q], t1);                                            \
            }                                                                         \
            ull h0p = act2(gp0[0], gp0[1], gp0[2], gp0[3], cs[0], cs[1]);             \
            ull h1p = act2(gp1[0], gp1[1], gp1[2], gp1[3], cs[2], cs[3]);              \
            *reinterpret_cast<ulonglong2*>(&sm.hb1[NXT][j][4 * kh]) =                 \
                make_ulonglong2(h0p, h1p);                                            \
        }                                                                             \
        __syncthreads();                                                              \
    }

__global__ void __launch_bounds__(NTHR, 1)
lstm_persistent_kernel(const float* __restrict__ x,
                       const float* __restrict__ Wih1, const float* __restrict__ Whh1,
                       const float* __restrict__ bih1, const float* __restrict__ bhh1,
                       const float* __restrict__ Wih2, const float* __restrict__ Whh2,
                       const float* __restrict__ bih2, const float* __restrict__ bhh2,
                       const float* __restrict__ Wlin, const float* __restrict__ blin,
                       float* __restrict__ out) {
    extern __shared__ char smem_raw[];
    Smem& sm = *reinterpret_cast<Smem*>(smem_raw);

    const int tid  = threadIdx.x;
    const int wid  = tid >> 5;
    const int lane = tid & 31;
    const int row0 = blockIdx.x * NR;

    // ---- one-time staging ----
    for (int i = tid; i < GATES * HID; i += NTHR) {
        int gsrc = i >> 6, k = i & 63;
        int col = (gsrc & 63) * 4 + (gsrc >> 6);
        sm.W1[k][col]      = Whh1[i];
        sm.W2[k][col]      = Wih2[i];
        sm.W2[64 + k][col] = Whh2[i];
    }
    for (int gsrc = tid; gsrc < GATES; gsrc += NTHR) {
        int col = (gsrc & 63) * 4 + (gsrc >> 6);
        sm.wih1v[col] = Wih1[gsrc];
        sm.b1v[col]   = bih1[gsrc] + bhh1[gsrc];
        sm.b2v[col]   = bih2[gsrc] + bhh2[gsrc];
    }
    if (tid < HID) sm.wlin[tid] = Wlin[tid];
    if (tid == 0)  sm.blin = blin[0];
    for (int i = tid; i < 2 * HID * NR; i += NTHR) {
        reinterpret_cast<float*>(sm.hb1)[i] = 0.0f;
        reinterpret_cast<float*>(sm.hb2)[i] = 0.0f;
    }
    // stage x transposed: xT[t][row]; coalesced LDG along t
    for (int i = tid; i < NR * SEQ; i += NTHR) {
        int row = i >> 9, t = i & (SEQ - 1);
        sm.xT[t][row] = x[(row0 + row) * SEQ + t];
    }
    if (tid < NR) sm.xT[SEQ][tid] = 0.0f;   // pad row (h1(SEQ) unused)
    __syncthreads();

    const bool isL1 = (wid >= 8);
    const int kq   = lane >> 3;                      // L2 k-quarter / owned pair
    const int kh   = lane >> 4;                      // L1 k-half
    const int j    = isL1 ? ((wid - 8) * 16 + (lane & 15)) : (wid * 8 + (lane & 7));
    const int c4   = j * 4;

    // register-resident weight cache: first 8 k-slices of this thread's strip
    float4 wreg[8];
    // loop-invariant bias / wih1, pre-packed f32x2 (off the ACT critical path)
    ull biasd[4];
    ull wd[4];
    if (!isL1) {
        const float* wp = &sm.W2[kq][c4];
#pragma unroll
        for (int m = 0; m < 8; m++)
            wreg[m] = *reinterpret_cast<const float4*>(wp + m * 4 * GATES);
        float4 bv = *reinterpret_cast<const float4*>(&sm.b2v[c4]);
        biasd[0] = pk2(bv.x, bv.x); biasd[1] = pk2(bv.y, bv.y);
        biasd[2] = pk2(bv.z, bv.z); biasd[3] = pk2(bv.w, bv.w);
        wd[0] = wd[1] = wd[2] = wd[3] = 0ull;
    } else {
        const float* wp = &sm.W1[kh][c4];
#pragma unroll
        for (int m = 0; m < 8; m++)
            wreg[m] = *reinterpret_cast<const float4*>(wp + m * 2 * GATES);
        float4 bv  = *reinterpret_cast<const float4*>(&sm.b1v[c4]);
        float4 wiv = *reinterpret_cast<const float4*>(&sm.wih1v[c4]);
        biasd[0] = pk2(bv.x, bv.x); biasd[1] = pk2(bv.y, bv.y);
        biasd[2] = pk2(bv.z, bv.z); biasd[3] = pk2(bv.w, bv.w);
        wd[0] = pk2(wiv.x, wiv.x); wd[1] = pk2(wiv.y, wiv.y);
        wd[2] = pk2(wiv.z, wiv.z); wd[3] = pk2(wiv.w, wiv.w);
    }

    float cs[4] = {0.f, 0.f, 0.f, 0.f};
    const float wl = sm.wlin[j];

    // ---- prologue: h1(0) = act(b1 + x(0)*wih1), L1 warps -> hb1[0] ----
    if (isL1) {
        ulonglong2 xq = *reinterpret_cast<const ulonglong2*>(&sm.xT[0][4 * kh]);
        ull gp0[4], gp1[4];
#pragma unroll
        for (int q = 0; q < 4; q++) {
            gp0[q] = biasd[q]; fma2(gp0[q], xq.x, wd[q]);
            gp1[q] = biasd[q]; fma2(gp1[q], xq.y, wd[q]);
        }
        ull h0p = act2(gp0[0], gp0[1], gp0[2], gp0[3], cs[0], cs[1]);
        ull h1p = act2(gp1[0], gp1[1], gp1[2], gp1[3], cs[2], cs[3]);
        *reinterpret_cast<ulonglong2*>(&sm.hb1[0][j][4 * kh]) = make_ulonglong2(h0p, h1p);
    }
    __syncthreads();

    // unrolled x2: compile-time parity per copy
    for (int t = 0; t < SEQ; t += 2) {
        STEP_BODY(0, 1, t)
        STEP_BODY(1, 0, t + 1)
    }

    // finalize out[SEQ-1] from outp[SEQ & 1]
    if (tid < NR) {
        const float* op = &sm.outp[SEQ & 1][tid >> 1][tid & 1][0];
        float4 a = *reinterpret_cast<const float4*>(op);
        float4 b = *reinterpret_cast<const float4*>(op + 4);
        out[(row0 + tid) * SEQ + (SEQ - 1)] =
            sm.blin + ((a.x + a.y) + (a.z + a.w)) + ((b.x + b.y) + (b.z + b.w));
    }
}

extern "C" void kernel_launch(void* const* d_in, const int* in_sizes, int n_in,
                              void* d_out, int out_size) {
    const float* x     = (const float*)d_in[0];
    const float* Wih1  = (const float*)d_in[1];
    const float* Whh1  = (const float*)d_in[2];
    const float* bih1  = (const float*)d_in[3];
    const float* bhh1  = (const float*)d_in[4];
    const float* Wih2  = (const float*)d_in[5];
    const float* Whh2  = (const float*)d_in[6];
    const float* bih2  = (const float*)d_in[7];
    const float* bhh2  = (const float*)d_in[8];
    const float* Wlin  = (const float*)d_in[9];
    const float* blin  = (const float*)d_in[10];
    float* out = (float*)d_out;

    (void)in_sizes; (void)n_in; (void)out_size;

    static_assert(sizeof(Smem) <= 232448, "smem over sm_103a opt-in limit");
    cudaFuncSetAttribute(lstm_persistent_kernel,
                         cudaFuncAttributeMaxDynamicSharedMemorySize,
                         (int)sizeof(Smem));
    lstm_persistent_kernel<<<NCTA, NTHR, sizeof(Smem)>>>(
        x, Wih1, Whh1, bih1, bhh1, Wih2, Whh2, bih2, bhh2, Wlin, blin, out);
}